// round 1
// baseline (speedup 1.0000x reference)
#include <cuda_runtime.h>
#include <math.h>

// Problem constants
#define N_ROWS 8192
#define F_IN   512
#define H_DIM  256
#define W_DIM  64

// Tiling
#define TM     32          // rows per block
#define KT     32          // k-chunk
#define NBLK   (N_ROWS / TM)   // 256 blocks
#define NTHR   128

// Shared memory layout (floats)
#define XS_STRIDE  33
#define ACT_STRIDE 260
#define XS_OFF   0
#define WS_OFF   (TM * XS_STRIDE)                  // 1056
#define ACT_OFF  (WS_OFF + KT * H_DIM)             // 9248
#define RED_OFF  (ACT_OFF + TM * ACT_STRIDE)       // 17568
#define SMEM_FLOATS (RED_OFF + 8)
#define SMEM_BYTES  (SMEM_FLOATS * 4)

// Per-block partial sums (device scratch: no allocation allowed)
__device__ float g_partials[NBLK];

// Fused MLP: enc1 = relu(X@W1+b1); enc2 = relu(enc1@W2+b2);
// t_n = sum_w tanh(enc2@Wq + bq)_w * Wh_w ; block partial = sum over its rows.
__global__ void __launch_bounds__(NTHR) mlp_kernel(
    const float* __restrict__ X,
    const float* __restrict__ W1, const float* __restrict__ b1,
    const float* __restrict__ W2, const float* __restrict__ b2,
    const float* __restrict__ Wq, const float* __restrict__ bq,
    const float* __restrict__ Wh)
{
    extern __shared__ float sm[];
    float* Xs  = sm + XS_OFF;    // [TM][XS_STRIDE]
    float* Ws  = sm + WS_OFF;    // [KT][H_DIM] (or [KT][W_DIM] in phase C)
    float* Act = sm + ACT_OFF;   // [TM][ACT_STRIDE]
    float* red = sm + RED_OFF;   // [4]

    const int tid = threadIdx.x;
    const int tx  = tid & 31;    // lane
    const int ty  = tid >> 5;    // warp (0..3) -> 8 rows each
    const int n0  = blockIdx.x * TM;

    float acc[8][8];

    // ================= Phase A: enc1 = relu(X @ W1 + b1) =================
    #pragma unroll
    for (int i = 0; i < 8; ++i)
        #pragma unroll
        for (int j = 0; j < 8; ++j) acc[i][j] = 0.f;

    for (int k0 = 0; k0 < F_IN; k0 += KT) {
        __syncthreads();
        // X chunk [TM][KT], coalesced float4 loads, scalar stores (stride 33)
        #pragma unroll
        for (int i = 0; i < (TM * KT / 4) / NTHR; ++i) {   // 2
            int idx = i * NTHR + tid;
            int r = idx >> 3, c4 = idx & 7;
            float4 v = *reinterpret_cast<const float4*>(
                &X[(n0 + r) * F_IN + k0 + c4 * 4]);
            float* d = &Xs[r * XS_STRIDE + c4 * 4];
            d[0] = v.x; d[1] = v.y; d[2] = v.z; d[3] = v.w;
        }
        // W1 chunk [KT][H_DIM], float4 in/out
        #pragma unroll
        for (int i = 0; i < (KT * H_DIM / 4) / NTHR; ++i) { // 16
            int idx = i * NTHR + tid;
            int r = idx >> 6, c4 = idx & 63;
            *reinterpret_cast<float4*>(&Ws[r * H_DIM + c4 * 4]) =
                *reinterpret_cast<const float4*>(&W1[(k0 + r) * H_DIM + c4 * 4]);
        }
        __syncthreads();
        #pragma unroll 4
        for (int kk = 0; kk < KT; ++kk) {
            float a[8];
            #pragma unroll
            for (int i = 0; i < 8; ++i)   // lane-uniform -> broadcast LDS
                a[i] = Xs[(ty * 8 + i) * XS_STRIDE + kk];
            float4 bv0 = *reinterpret_cast<const float4*>(&Ws[kk * H_DIM + tx * 8]);
            float4 bv1 = *reinterpret_cast<const float4*>(&Ws[kk * H_DIM + tx * 8 + 4]);
            float b[8] = {bv0.x, bv0.y, bv0.z, bv0.w, bv1.x, bv1.y, bv1.z, bv1.w};
            #pragma unroll
            for (int i = 0; i < 8; ++i)
                #pragma unroll
                for (int j = 0; j < 8; ++j)
                    acc[i][j] = fmaf(a[i], b[j], acc[i][j]);
        }
    }
    __syncthreads();
    {
        float4 bb0 = *reinterpret_cast<const float4*>(&b1[tx * 8]);
        float4 bb1 = *reinterpret_cast<const float4*>(&b1[tx * 8 + 4]);
        float bias[8] = {bb0.x, bb0.y, bb0.z, bb0.w, bb1.x, bb1.y, bb1.z, bb1.w};
        #pragma unroll
        for (int i = 0; i < 8; ++i) {
            float4 o0, o1;
            o0.x = fmaxf(acc[i][0] + bias[0], 0.f);
            o0.y = fmaxf(acc[i][1] + bias[1], 0.f);
            o0.z = fmaxf(acc[i][2] + bias[2], 0.f);
            o0.w = fmaxf(acc[i][3] + bias[3], 0.f);
            o1.x = fmaxf(acc[i][4] + bias[4], 0.f);
            o1.y = fmaxf(acc[i][5] + bias[5], 0.f);
            o1.z = fmaxf(acc[i][6] + bias[6], 0.f);
            o1.w = fmaxf(acc[i][7] + bias[7], 0.f);
            float* d = &Act[(ty * 8 + i) * ACT_STRIDE + tx * 8];
            *reinterpret_cast<float4*>(d)     = o0;
            *reinterpret_cast<float4*>(d + 4) = o1;
        }
    }

    // ================= Phase B: enc2 = relu(enc1 @ W2 + b2) =================
    #pragma unroll
    for (int i = 0; i < 8; ++i)
        #pragma unroll
        for (int j = 0; j < 8; ++j) acc[i][j] = 0.f;

    for (int k0 = 0; k0 < H_DIM; k0 += KT) {
        __syncthreads();   // also orders Act stores (phase A) before reads
        #pragma unroll
        for (int i = 0; i < (KT * H_DIM / 4) / NTHR; ++i) { // 16
            int idx = i * NTHR + tid;
            int r = idx >> 6, c4 = idx & 63;
            *reinterpret_cast<float4*>(&Ws[r * H_DIM + c4 * 4]) =
                *reinterpret_cast<const float4*>(&W2[(k0 + r) * H_DIM + c4 * 4]);
        }
        __syncthreads();
        #pragma unroll 4
        for (int kk = 0; kk < KT; ++kk) {
            float a[8];
            #pragma unroll
            for (int i = 0; i < 8; ++i)
                a[i] = Act[(ty * 8 + i) * ACT_STRIDE + k0 + kk];
            float4 bv0 = *reinterpret_cast<const float4*>(&Ws[kk * H_DIM + tx * 8]);
            float4 bv1 = *reinterpret_cast<const float4*>(&Ws[kk * H_DIM + tx * 8 + 4]);
            float b[8] = {bv0.x, bv0.y, bv0.z, bv0.w, bv1.x, bv1.y, bv1.z, bv1.w};
            #pragma unroll
            for (int i = 0; i < 8; ++i)
                #pragma unroll
                for (int j = 0; j < 8; ++j)
                    acc[i][j] = fmaf(a[i], b[j], acc[i][j]);
        }
    }
    __syncthreads();       // all reads of Act(enc1) done before overwrite
    {
        float4 bb0 = *reinterpret_cast<const float4*>(&b2[tx * 8]);
        float4 bb1 = *reinterpret_cast<const float4*>(&b2[tx * 8 + 4]);
        float bias[8] = {bb0.x, bb0.y, bb0.z, bb0.w, bb1.x, bb1.y, bb1.z, bb1.w};
        #pragma unroll
        for (int i = 0; i < 8; ++i) {
            float4 o0, o1;
            o0.x = fmaxf(acc[i][0] + bias[0], 0.f);
            o0.y = fmaxf(acc[i][1] + bias[1], 0.f);
            o0.z = fmaxf(acc[i][2] + bias[2], 0.f);
            o0.w = fmaxf(acc[i][3] + bias[3], 0.f);
            o1.x = fmaxf(acc[i][4] + bias[4], 0.f);
            o1.y = fmaxf(acc[i][5] + bias[5], 0.f);
            o1.z = fmaxf(acc[i][6] + bias[6], 0.f);
            o1.w = fmaxf(acc[i][7] + bias[7], 0.f);
            float* d = &Act[(ty * 8 + i) * ACT_STRIDE + tx * 8];
            *reinterpret_cast<float4*>(d)     = o0;
            *reinterpret_cast<float4*>(d + 4) = o1;
        }
    }

    // ========= Phase C: z = enc2 @ Wq; t = sum tanh(z+bq)*Wh ; reduce =========
    float accC[8][2];
    #pragma unroll
    for (int i = 0; i < 8; ++i) { accC[i][0] = 0.f; accC[i][1] = 0.f; }

    for (int k0 = 0; k0 < H_DIM; k0 += KT) {
        __syncthreads();   // orders Act(enc2) stores before reads / Ws reuse
        #pragma unroll
        for (int i = 0; i < (KT * W_DIM / 4) / NTHR; ++i) { // 4
            int idx = i * NTHR + tid;
            int r = idx >> 4, c4 = idx & 15;
            *reinterpret_cast<float4*>(&Ws[r * W_DIM + c4 * 4]) =
                *reinterpret_cast<const float4*>(&Wq[(k0 + r) * W_DIM + c4 * 4]);
        }
        __syncthreads();
        #pragma unroll 4
        for (int kk = 0; kk < KT; ++kk) {
            float a[8];
            #pragma unroll
            for (int i = 0; i < 8; ++i)
                a[i] = Act[(ty * 8 + i) * ACT_STRIDE + k0 + kk];
            float2 bv = *reinterpret_cast<const float2*>(&Ws[kk * W_DIM + tx * 2]);
            #pragma unroll
            for (int i = 0; i < 8; ++i) {
                accC[i][0] = fmaf(a[i], bv.x, accC[i][0]);
                accC[i][1] = fmaf(a[i], bv.y, accC[i][1]);
            }
        }
    }

    // Epilogue: tanh + dot with Wh, deterministic block reduction
    float bq0 = __ldg(&bq[tx * 2]),     bq1 = __ldg(&bq[tx * 2 + 1]);
    float wh0 = __ldg(&Wh[tx * 2]),     wh1 = __ldg(&Wh[tx * 2 + 1]);
    float t = 0.f;
    #pragma unroll
    for (int i = 0; i < 8; ++i) {
        t += tanhf(accC[i][0] + bq0) * wh0;
        t += tanhf(accC[i][1] + bq1) * wh1;
    }
    #pragma unroll
    for (int s = 16; s > 0; s >>= 1)
        t += __shfl_xor_sync(0xffffffffu, t, s);
    if (tx == 0) red[ty] = t;
    __syncthreads();
    if (tid == 0)
        g_partials[blockIdx.x] = (red[0] + red[1]) + (red[2] + red[3]);
}

// Deterministic final reduction of the 256 block partials.
__global__ void reduce_kernel(const float* __restrict__ bh, float* __restrict__ out)
{
    __shared__ float s[NBLK];
    int t = threadIdx.x;
    s[t] = g_partials[t];
    __syncthreads();
    #pragma unroll
    for (int step = NBLK / 2; step > 0; step >>= 1) {
        if (t < step) s[t] += s[t + step];
        __syncthreads();
    }
    if (t == 0) out[0] = s[0] + bh[0];
}

extern "C" void kernel_launch(void* const* d_in, const int* in_sizes, int n_in,
                              void* d_out, int out_size)
{
    const float* X  = (const float*)d_in[0];
    const float* W1 = (const float*)d_in[1];
    const float* b1 = (const float*)d_in[2];
    const float* W2 = (const float*)d_in[3];
    const float* b2 = (const float*)d_in[4];
    const float* Wq = (const float*)d_in[5];
    const float* bq = (const float*)d_in[6];
    const float* Wh = (const float*)d_in[7];
    const float* bh = (const float*)d_in[8];
    float* out = (float*)d_out;

    cudaFuncSetAttribute(mlp_kernel,
                         cudaFuncAttributeMaxDynamicSharedMemorySize, SMEM_BYTES);
    mlp_kernel<<<NBLK, NTHR, SMEM_BYTES>>>(X, W1, b1, W2, b2, Wq, bq, Wh);
    reduce_kernel<<<1, NBLK>>>(bh, out);
}

// round 7
// speedup vs baseline: 1.7624x; 1.7624x over previous
#include <cuda_runtime.h>
#include <cuda_bf16.h>
#include <mma.h>
#include <math.h>
#include <stdint.h>

using namespace nvcuda;

// ---------------- problem constants ----------------
#define N_ROWS 8192
#define F_IN   512
#define H_DIM  256
#define W_DIM  64

#define RT     64                  // rows per CTA
#define NCTA   (N_ROWS / RT)       // 128
#define NTHR   256                 // 8 warps: 2 (m) x 4 (n)
#define KC     32                  // k-chunk

// smem strides (elements)
#define XS_LD  40
#define WS_LD  264
#define A_LD   264
#define W3_LD  72
#define SC_LD  264
#define SC3_LD 72

// smem offsets (bytes)
#define OFF_A2H 0
#define OFF_A2L (OFF_A2H + RT * A_LD * 2)      // 33792
#define OFF_WS  (OFF_A2L + RT * A_LD * 2)      // 67584
#define WS_BUF  (KC * WS_LD * 2 * 2)           // 33792 per buffer (hi+lo)
#define WS_HI   (KC * WS_LD * 2)               // 16896
#define OFF_XS  (OFF_WS + 2 * WS_BUF)          // 135168
#define XS_BUF  (RT * XS_LD * 2 * 2)           // 10240 per buffer (hi+lo)
#define XS_HI   (RT * XS_LD * 2)               // 5120
#define OFF_RED (OFF_XS + 2 * XS_BUF)          // 155648
#define SMEM_SZ (OFF_RED + 256)                // 155904
#define W3_BUF  (KC * W3_LD * 2 * 2)           // 9216
#define W3_HI   (KC * W3_LD * 2)               // 4608

// ---------------- global scratch (no runtime alloc allowed) ----------------
__device__ __align__(16) __nv_bfloat16 g_Xh [N_ROWS * F_IN];
__device__ __align__(16) __nv_bfloat16 g_Xl [N_ROWS * F_IN];
__device__ __align__(16) __nv_bfloat16 g_W1h[F_IN * H_DIM];
__device__ __align__(16) __nv_bfloat16 g_W1l[F_IN * H_DIM];
__device__ __align__(16) __nv_bfloat16 g_W2h[H_DIM * H_DIM];
__device__ __align__(16) __nv_bfloat16 g_W2l[H_DIM * H_DIM];
__device__ __align__(16) __nv_bfloat16 g_Wqh[H_DIM * W_DIM];
__device__ __align__(16) __nv_bfloat16 g_Wql[H_DIM * W_DIM];
__device__ float g_partials[NCTA];

// ---------------- helpers ----------------
__device__ __forceinline__ uint32_t smem_u32(const void* p) {
    uint32_t a;
    asm("{ .reg .u64 t; cvta.to.shared.u64 t, %1; cvt.u32.u64 %0, t; }" : "=r"(a) : "l"(p));
    return a;
}
__device__ __forceinline__ void cpa16(uint32_t s, const void* g) {
    asm volatile("cp.async.cg.shared.global [%0], [%1], 16;"
                 :: "r"(s), "l"(__cvta_generic_to_global(g)));
}
#define CP_COMMIT() asm volatile("cp.async.commit_group;" ::: "memory")
#define CP_WAIT(n)  asm volatile("cp.async.wait_group %0;" :: "n"(n) : "memory")

// split float pair into packed bf16 hi + bf16 residual lo
__device__ __forceinline__ void split_pack(float a, float b, uint32_t& hi, uint32_t& lo) {
    __nv_bfloat16 ha = __float2bfloat16(a), hb = __float2bfloat16(b);
    float ra = a - __bfloat162float(ha), rb = b - __bfloat162float(hb);
    __nv_bfloat16 la = __float2bfloat16(ra), lb = __float2bfloat16(rb);
    hi = (uint32_t)__bfloat16_as_ushort(ha) | ((uint32_t)__bfloat16_as_ushort(hb) << 16);
    lo = (uint32_t)__bfloat16_as_ushort(la) | ((uint32_t)__bfloat16_as_ushort(lb) << 16);
}

// ---------------- prep kernel: fp32 -> bf16 hi/lo split (no layout change) ----------------
#define XP   (N_ROWS * F_IN / 2)           // 2097152 pairs
#define W1P  (F_IN * H_DIM / 2)            // 65536
#define W2P  (H_DIM * H_DIM / 2)           // 32768
#define WQP  (H_DIM * W_DIM / 2)           // 8192
#define TOTP (XP + W1P + W2P + WQP)        // 2203648 = 4304 * 512

__global__ void __launch_bounds__(512) prep_kernel(
    const float* __restrict__ X,  const float* __restrict__ W1,
    const float* __restrict__ W2, const float* __restrict__ Wq)
{
    unsigned i = blockIdx.x * 512u + threadIdx.x;
    const float* src; uint32_t* dh; uint32_t* dl; unsigned j;
    if (i < XP)                  { src = X;  j = i;                 dh = (uint32_t*)g_Xh;  dl = (uint32_t*)g_Xl;  }
    else if (i < XP + W1P)       { src = W1; j = i - XP;            dh = (uint32_t*)g_W1h; dl = (uint32_t*)g_W1l; }
    else if (i < XP + W1P + W2P) { src = W2; j = i - XP - W1P;      dh = (uint32_t*)g_W2h; dl = (uint32_t*)g_W2l; }
    else                         { src = Wq; j = i - XP - W1P - W2P; dh = (uint32_t*)g_Wqh; dl = (uint32_t*)g_Wql; }
    float2 v = reinterpret_cast<const float2*>(src)[j];
    uint32_t hi, lo; split_pack(v.x, v.y, hi, lo);
    dh[j] = hi; dl[j] = lo;
}

// ---------------- one k-step of the 3-term split GEMM ----------------
template<int NF, int LDA, int LDB>
__device__ __forceinline__ void do_kstep(
    wmma::fragment<wmma::accumulator, 16, 16, 16, float> (&acc)[2][NF],
    const __nv_bfloat16* aH, const __nv_bfloat16* aL,
    const __nv_bfloat16* bH, const __nv_bfloat16* bL)
{
    wmma::fragment<wmma::matrix_a, 16, 16, 16, __nv_bfloat16, wmma::row_major> ah[2], al[2];
    wmma::fragment<wmma::matrix_b, 16, 16, 16, __nv_bfloat16, wmma::row_major> bh[NF], bl[NF];
    #pragma unroll
    for (int i = 0; i < 2; ++i) {
        wmma::load_matrix_sync(ah[i], aH + i * 16 * LDA, LDA);
        wmma::load_matrix_sync(al[i], aL + i * 16 * LDA, LDA);
    }
    #pragma unroll
    for (int j = 0; j < NF; ++j) {
        wmma::load_matrix_sync(bh[j], bH + j * 16, LDB);
        wmma::load_matrix_sync(bl[j], bL + j * 16, LDB);
    }
    #pragma unroll
    for (int i = 0; i < 2; ++i)
        #pragma unroll
        for (int j = 0; j < NF; ++j) {
            wmma::mma_sync(acc[i][j], ah[i], bh[j], acc[i][j]);
            wmma::mma_sync(acc[i][j], ah[i], bl[j], acc[i][j]);
            wmma::mma_sync(acc[i][j], al[i], bh[j], acc[i][j]);
        }
}

// ---------------- main fused MLP kernel ----------------
__global__ void __launch_bounds__(NTHR) mlp_main(
    const float* __restrict__ b1, const float* __restrict__ b2,
    const float* __restrict__ bq, const float* __restrict__ Wh)
{
    extern __shared__ char smem[];
    const uint32_t sb = smem_u32(smem);
    const int tid  = threadIdx.x;
    const int lane = tid & 31, wid = tid >> 5;
    const int wm = wid & 1, wn = wid >> 1;     // 2 x 4 warp grid
    const int row0 = blockIdx.x * RT;

    typedef wmma::fragment<wmma::accumulator, 16, 16, 16, float> AccFrag;

    __nv_bfloat16* a2h = (__nv_bfloat16*)(smem + OFF_A2H);
    __nv_bfloat16* a2l = (__nv_bfloat16*)(smem + OFF_A2L);

    // ---- staging lambdas (all 256 threads participate) ----
    auto stage_l1 = [&](int c, int buf) {
        int k0 = c * KC;
        {   // X chunk: 64 rows x 32 cols (hi + lo)
            int r = tid >> 2, q = tid & 3;
            uint32_t dx = sb + OFF_XS + buf * XS_BUF + r * (XS_LD * 2) + q * 16;
            cpa16(dx,         g_Xh + (size_t)(row0 + r) * F_IN + k0 + q * 8);
            cpa16(dx + XS_HI, g_Xl + (size_t)(row0 + r) * F_IN + k0 + q * 8);
        }
        // W1 chunk: 32 rows x 256 cols (hi + lo)
        #pragma unroll
        for (int it = 0; it < 4; ++it) {
            int idx = tid + it * NTHR;
            int r = idx >> 5, q = idx & 31;
            uint32_t dw = sb + OFF_WS + buf * WS_BUF + r * (WS_LD * 2) + q * 16;
            cpa16(dw,         g_W1h + (size_t)(k0 + r) * H_DIM + q * 8);
            cpa16(dw + WS_HI, g_W1l + (size_t)(k0 + r) * H_DIM + q * 8);
        }
    };
    auto stage_w2 = [&](int c, int buf) {
        int k0 = c * KC;
        #pragma unroll
        for (int it = 0; it < 4; ++it) {
            int idx = tid + it * NTHR;
            int r = idx >> 5, q = idx & 31;
            uint32_t dw = sb + OFF_WS + buf * WS_BUF + r * (WS_LD * 2) + q * 16;
            cpa16(dw,         g_W2h + (size_t)(k0 + r) * H_DIM + q * 8);
            cpa16(dw + WS_HI, g_W2l + (size_t)(k0 + r) * H_DIM + q * 8);
        }
    };
    auto stage_w3 = [&](int c, int buf) {
        int k0 = c * KC;
        int r = tid >> 3, q = tid & 7;         // 32 rows x 8 quanta = 256
        uint32_t dw = sb + OFF_WS + buf * W3_BUF + r * (W3_LD * 2) + q * 16;
        cpa16(dw,         g_Wqh + (size_t)(k0 + r) * W_DIM + q * 8);
        cpa16(dw + W3_HI, g_Wql + (size_t)(k0 + r) * W_DIM + q * 8);
    };

    // ================= layer 1: C1 = X @ W1 =================
    AccFrag acc[2][4];
    #pragma unroll
    for (int i = 0; i < 2; ++i)
        #pragma unroll
        for (int j = 0; j < 4; ++j) wmma::fill_fragment(acc[i][j], 0.0f);

    stage_l1(0, 0); CP_COMMIT();
    for (int c = 0; c < F_IN / KC; ++c) {        // 16 chunks
        if (c < F_IN / KC - 1) { stage_l1(c + 1, (c + 1) & 1); CP_COMMIT(); CP_WAIT(1); }
        else                   { CP_WAIT(0); }
        __syncthreads();
        const __nv_bfloat16* xsH = (const __nv_bfloat16*)(smem + OFF_XS + (c & 1) * XS_BUF);
        const __nv_bfloat16* xsL = xsH + RT * XS_LD;
        const __nv_bfloat16* wsH = (const __nv_bfloat16*)(smem + OFF_WS + (c & 1) * WS_BUF);
        const __nv_bfloat16* wsL = wsH + KC * WS_LD;
        #pragma unroll
        for (int ks = 0; ks < 2; ++ks)
            do_kstep<4, XS_LD, WS_LD>(acc,
                xsH + wm * 32 * XS_LD + ks * 16, xsL + wm * 32 * XS_LD + ks * 16,
                wsH + ks * 16 * WS_LD + wn * 64, wsL + ks * 16 * WS_LD + wn * 64);
        __syncthreads();
    }
    // epilogue 1: bias + relu + split -> A2
    {
        float* sc = (float*)(smem + OFF_WS);
        #pragma unroll
        for (int i = 0; i < 2; ++i)
            #pragma unroll
            for (int j = 0; j < 4; ++j)
                wmma::store_matrix_sync(sc + (wm * 32 + i * 16) * SC_LD + wn * 64 + j * 16,
                                        acc[i][j], SC_LD, wmma::mem_row_major);
        __syncthreads();
        int r = tid >> 2, s = tid & 3;
        #pragma unroll
        for (int j = 0; j < 64; ++j) {
            int col = s + j * 4;
            float v = fmaxf(sc[r * SC_LD + col] + __ldg(&b1[col]), 0.0f);
            __nv_bfloat16 h = __float2bfloat16(v);
            __nv_bfloat16 l = __float2bfloat16(v - __bfloat162float(h));
            a2h[r * A_LD + col] = h; a2l[r * A_LD + col] = l;
        }
        __syncthreads();
    }

    // ================= layer 2: C2 = A2 @ W2 =================
    #pragma unroll
    for (int i = 0; i < 2; ++i)
        #pragma unroll
        for (int j = 0; j < 4; ++j) wmma::fill_fragment(acc[i][j], 0.0f);

    stage_w2(0, 0); CP_COMMIT();
    for (int c = 0; c < H_DIM / KC; ++c) {       // 8 chunks
        if (c < H_DIM / KC - 1) { stage_w2(c + 1, (c + 1) & 1); CP_COMMIT(); CP_WAIT(1); }
        else                    { CP_WAIT(0); }
        __syncthreads();
        const __nv_bfloat16* wsH = (const __nv_bfloat16*)(smem + OFF_WS + (c & 1) * WS_BUF);
        const __nv_bfloat16* wsL = wsH + KC * WS_LD;
        #pragma unroll
        for (int ks = 0; ks < 2; ++ks)
            do_kstep<4, A_LD, WS_LD>(acc,
                a2h + wm * 32 * A_LD + c * KC + ks * 16, a2l + wm * 32 * A_LD + c * KC + ks * 16,
                wsH + ks * 16 * WS_LD + wn * 64,         wsL + ks * 16 * WS_LD + wn * 64);
        __syncthreads();
    }
    // epilogue 2: bias + relu + split -> A2 (overwrite)
    {
        float* sc = (float*)(smem + OFF_WS);
        #pragma unroll
        for (int i = 0; i < 2; ++i)
            #pragma unroll
            for (int j = 0; j < 4; ++j)
                wmma::store_matrix_sync(sc + (wm * 32 + i * 16) * SC_LD + wn * 64 + j * 16,
                                        acc[i][j], SC_LD, wmma::mem_row_major);
        __syncthreads();
        int r = tid >> 2, s = tid & 3;
        #pragma unroll
        for (int j = 0; j < 64; ++j) {
            int col = s + j * 4;
            float v = fmaxf(sc[r * SC_LD + col] + __ldg(&b2[col]), 0.0f);
            __nv_bfloat16 h = __float2bfloat16(v);
            __nv_bfloat16 l = __float2bfloat16(v - __bfloat162float(h));
            a2h[r * A_LD + col] = h; a2l[r * A_LD + col] = l;
        }
        __syncthreads();
    }

    // ================= layer 3: C3 = A2 @ Wq =================
    AccFrag acc3[2][1];
    wmma::fill_fragment(acc3[0][0], 0.0f);
    wmma::fill_fragment(acc3[1][0], 0.0f);

    stage_w3(0, 0); CP_COMMIT();
    for (int c = 0; c < H_DIM / KC; ++c) {       // 8 chunks
        if (c < H_DIM / KC - 1) { stage_w3(c + 1, (c + 1) & 1); CP_COMMIT(); CP_WAIT(1); }
        else                    { CP_WAIT(0); }
        __syncthreads();
        const __nv_bfloat16* w3H = (const __nv_bfloat16*)(smem + OFF_WS + (c & 1) * W3_BUF);
        const __nv_bfloat16* w3L = w3H + KC * W3_LD;
        #pragma unroll
        for (int ks = 0; ks < 2; ++ks)
            do_kstep<1, A_LD, W3_LD>(acc3,
                a2h + wm * 32 * A_LD + c * KC + ks * 16, a2l + wm * 32 * A_LD + c * KC + ks * 16,
                w3H + ks * 16 * W3_LD + wn * 16,         w3L + ks * 16 * W3_LD + wn * 16);
        __syncthreads();
    }
    // epilogue 3: tanh + dot(Wh) + deterministic reduction
    {
        float* sc3 = (float*)(smem + OFF_WS);
        #pragma unroll
        for (int i = 0; i < 2; ++i)
            wmma::store_matrix_sync(sc3 + (wm * 32 + i * 16) * SC3_LD + wn * 16,
                                    acc3[i][0], SC3_LD, wmma::mem_row_major);
        __syncthreads();
        int r = tid >> 2, s = tid & 3;
        float t = 0.0f;
        #pragma unroll
        for (int j = 0; j < 16; ++j) {
            int col = s + j * 4;
            t += tanhf(sc3[r * SC3_LD + col] + __ldg(&bq[col])) * __ldg(&Wh[col]);
        }
        t += __shfl_down_sync(0xffffffffu, t, 2);
        t += __shfl_down_sync(0xffffffffu, t, 1);
        if (s == 0) ((float*)(smem + OFF_RED))[r] = t;
        __syncthreads();
        if (wid == 0) {
            float* red = (float*)(smem + OFF_RED);
            float v = red[lane] + red[lane + 32];
            #pragma unroll
            for (int sh = 16; sh > 0; sh >>= 1)
                v += __shfl_xor_sync(0xffffffffu, v, sh);
            if (lane == 0) g_partials[blockIdx.x] = v;
        }
    }
}

// ---------------- final reduction ----------------
__global__ void reduce_kernel(const float* __restrict__ bh, float* __restrict__ out)
{
    __shared__ float s[NCTA];
    int t = threadIdx.x;
    s[t] = g_partials[t];
    __syncthreads();
    #pragma unroll
    for (int st = NCTA / 2; st > 0; st >>= 1) {
        if (t < st) s[t] += s[t + st];
        __syncthreads();
    }
    if (t == 0) out[0] = s[0] + bh[0];
}

extern "C" void kernel_launch(void* const* d_in, const int* in_sizes, int n_in,
                              void* d_out, int out_size)
{
    const float* X  = (const float*)d_in[0];
    const float* W1 = (const float*)d_in[1];
    const float* b1 = (const float*)d_in[2];
    const float* W2 = (const float*)d_in[3];
    const float* b2 = (const float*)d_in[4];
    const float* Wq = (const float*)d_in[5];
    const float* bq = (const float*)d_in[6];
    const float* Wh = (const float*)d_in[7];
    const float* bh = (const float*)d_in[8];
    float* out = (float*)d_out;

    prep_kernel<<<TOTP / 512, 512>>>(X, W1, W2, Wq);
    cudaFuncSetAttribute(mlp_main, cudaFuncAttributeMaxDynamicSharedMemorySize, SMEM_SZ);
    mlp_main<<<NCTA, NTHR, SMEM_SZ>>>(b1, b2, bq, Wh);
    reduce_kernel<<<1, NCTA>>>(bh, out);
}